// round 14
// baseline (speedup 1.0000x reference)
#include <cuda_runtime.h>
#include <cuda_fp16.h>

#define NN 16
#define VV 5023
#define FF 9976
#define HH 512
#define WW 512
#define NV (NN * VV)            // 80368
#define NF (NN * FF)            // 159616
#define NPIX (NN * HH * WW)     // 4194304
#define MMBLK 314               // blocks that produce minmax partials
#define K1GRID ((NF + 255) / 256)   // 624

__device__ float g_pmn[MMBLK];
__device__ float g_pmx[MMBLK];
__device__ float2 g_mR;         // {m, 1/R}
__device__ int g_done;          // zero-init; self-resets each run
__device__ float2 g_fz8[NF];    // 8B/(image,face): z0 fp32 (raw) + (z1-z0,z2-z0) fp16x2 (raw)

// Branch-free predicated 8B gather: single @p LDG.E.64.NC, no BSSY/BSYNC.
__device__ __forceinline__ float2 gather_pred(const float2* __restrict__ tab,
                                              int idx, int valid) {
    float2 r;
    const float2* addr = tab + (valid ? idx : 0);
    asm("{\n\t"
        ".reg .pred gp;\n\t"
        "setp.ne.s32 gp, %3, 0;\n\t"
        "mov.f32 %0, 0f00000000;\n\t"
        "mov.f32 %1, 0f00000000;\n\t"
        "@gp ld.global.nc.v2.f32 {%0,%1}, [%2];\n\t"
        "}"
        : "=f"(r.x), "=f"(r.y)
        : "l"(addr), "r"(valid));
    return r;
}

// ---------------------------------------------------------------------------
// Kernel 1: builds the RAW face-z table (independent of min/max) and computes
// min/max partials; last-finished partial block reduces them to g_mR={m,1/R}.
__global__ void __launch_bounds__(256) prep_kernel(const float* __restrict__ tv,
                                                   const int* __restrict__ faces) {
    const int tid = threadIdx.x;
    const int t = blockIdx.x * 256 + tid;
    __shared__ float smn[8], smx[8];
    __shared__ int is_last;

    // ---- raw face table: {z0, (z1-z0, z2-z0) fp16x2} -----------------------
    if (t < NF) {
        int n = t / FF;
        int f = t - n * FF;
        int v0 = __ldg(faces + 3 * f);
        int v1 = __ldg(faces + 3 * f + 1);
        int v2 = __ldg(faces + 3 * f + 2);
        long long vb = (long long)n * VV;
        float z0 = __ldg(tv + 3 * (vb + v0) + 2);
        float z1 = __ldg(tv + 3 * (vb + v1) + 2);
        float z2 = __ldg(tv + 3 * (vb + v2) + 2);
        __half2 d = __floats2half2_rn(z1 - z0, z2 - z0);
        float2 e;
        e.x = z0;
        e.y = __uint_as_float(*reinterpret_cast<unsigned int*>(&d));
        g_fz8[t] = e;
    }

    // ---- min/max partials over tv[:,:,2] (first MMBLK blocks only) ---------
    if (blockIdx.x < MMBLK) {
        float z = (t < NV) ? __ldg(tv + 3 * t + 2) : __ldg(tv + 2);
        float mn = z, mx = z;
        #pragma unroll
        for (int o = 16; o > 0; o >>= 1) {
            mn = fminf(mn, __shfl_xor_sync(0xFFFFFFFFu, mn, o));
            mx = fmaxf(mx, __shfl_xor_sync(0xFFFFFFFFu, mx, o));
        }
        int lane = tid & 31, w = tid >> 5;
        if (lane == 0) { smn[w] = mn; smx[w] = mx; }
        __syncthreads();
        if (tid == 0) {
            float bmn = smn[0], bmx = smx[0];
            #pragma unroll
            for (int k = 1; k < 8; k++) {
                bmn = fminf(bmn, smn[k]);
                bmx = fmaxf(bmx, smx[k]);
            }
            g_pmn[blockIdx.x] = bmn;
            g_pmx[blockIdx.x] = bmx;
            __threadfence();
            int c = atomicAdd(&g_done, 1);
            is_last = (c == MMBLK - 1);
        }
        __syncthreads();

        if (is_last) {
            float m = __int_as_float(0x7F800000);
            float M = -m;
            for (int k = tid; k < MMBLK; k += 256) {
                m = fminf(m, g_pmn[k]);
                M = fmaxf(M, g_pmx[k]);
            }
            #pragma unroll
            for (int o = 16; o > 0; o >>= 1) {
                m = fminf(m, __shfl_xor_sync(0xFFFFFFFFu, m, o));
                M = fmaxf(M, __shfl_xor_sync(0xFFFFFFFFu, M, o));
            }
            int lane = tid & 31, w = tid >> 5;
            if (lane == 0) { smn[w] = m; smx[w] = M; }
            __syncthreads();
            if (tid == 0) {
                float bm = smn[0], bM = smx[0];
                #pragma unroll
                for (int k = 1; k < 8; k++) {
                    bm = fminf(bm, smn[k]);
                    bM = fmaxf(bM, smx[k]);
                }
                float R = bM - bm;           // R = fl(M - m)
                g_mR = make_float2(bm, 1.0f / R);
                g_done = 0;                  // reset for next graph replay
            }
        }
    }
}

// ---------------------------------------------------------------------------
// Kernel 2: pixel interpolation. 8 px/thread: all 8 predicated gathers issued
// up front (2x per-warp gather MLP vs 4 px), then bary processed in two 4-px
// halves to bound register pressure. Streaming evict-first.
__global__ void __launch_bounds__(256) pixel_kernel(
    const float* __restrict__ bary,
    const int* __restrict__ p2f,
    float* __restrict__ out)
{
    int t = blockIdx.x * blockDim.x + threadIdx.x;
    long long base = (long long)t * 8;

    int4 pa = __ldcs(reinterpret_cast<const int4*>(p2f + base));
    int4 pb = __ldcs(reinterpret_cast<const int4*>(p2f + base) + 1);
    int ps[8] = {pa.x, pa.y, pa.z, pa.w, pb.x, pb.y, pb.z, pb.w};

    // All 8 gathers in flight before anything else depends on them.
    float2 e[8];
    #pragma unroll
    for (int i = 0; i < 8; i++)
        e[i] = gather_pred(g_fz8, ps[i], (int)(ps[i] >= 0));

    float2 mR = g_mR;          // uniform, L1-hit
    float m = mR.x, rcpR = mR.y;

    const float4* bp = reinterpret_cast<const float4*>(bary + base * 3);
    float4* op = reinterpret_cast<float4*>(out + base);

    #pragma unroll
    for (int h = 0; h < 2; h++) {
        float4 b0 = __ldcs(bp + 3 * h);
        float4 b1 = __ldcs(bp + 3 * h + 1);
        float4 b2 = __ldcs(bp + 3 * h + 2);
        float w[12] = {b0.x, b0.y, b0.z, b0.w, b1.x, b1.y,
                       b1.z, b1.w, b2.x, b2.y, b2.z, b2.w};
        float res[4];
        #pragma unroll
        for (int i = 0; i < 4; i++) {
            int px = 4 * h + i;
            float c1 = w[3 * i + 1], c2 = w[3 * i + 2];
            unsigned int db = __float_as_uint(e[px].y);
            __half2 dh = *reinterpret_cast<__half2*>(&db);
            float2 d = __half22float2(dh);
            float zbar = e[px].x - m + c1 * d.x + c2 * d.y;  // Σb·z - m (raw)
            float s = 1.0f - zbar * rcpR;
            res[i] = ps[px] >= 0 ? s : 0.0f;
        }
        __stcs(op + h, make_float4(res[0], res[1], res[2], res[3]));
    }
}

extern "C" void kernel_launch(void* const* d_in, const int* in_sizes, int n_in,
                              void* d_out, int out_size) {
    const float* tv = nullptr;      // 241104
    const float* bary = nullptr;    // 12582912
    const int* faces = nullptr;     // 29928
    const int* p2f = nullptr;       // 4194304
    for (int i = 0; i < n_in; i++) {
        switch (in_sizes[i]) {
            case NN * VV * 3:            tv    = (const float*)d_in[i]; break;
            case NN * HH * WW * 3:       bary  = (const float*)d_in[i]; break;
            case FF * 3:                 faces = (const int*)d_in[i];   break;
            case NN * HH * WW:           p2f   = (const int*)d_in[i];   break;
        }
    }
    float* out = (float*)d_out;

    prep_kernel<<<K1GRID, 256>>>(tv, faces);
    pixel_kernel<<<NPIX / 8 / 256, 256>>>(bary, p2f, out);
}

// round 15
// speedup vs baseline: 1.1891x; 1.1891x over previous
#include <cuda_runtime.h>
#include <cuda_fp16.h>

#define NN 16
#define VV 5023
#define FF 9976
#define HH 512
#define WW 512
#define NV (NN * VV)            // 80368
#define NF (NN * FF)            // 159616
#define NPIX (NN * HH * WW)     // 4194304
#define MMBLK 314               // blocks that produce minmax partials
#define K1GRID ((NF + 255) / 256)   // 624

__device__ float g_pmn[MMBLK];
__device__ float g_pmx[MMBLK];
__device__ float2 g_mR;         // {m, 1/R}
__device__ int g_done;          // zero-init; self-resets each run
__device__ float2 g_fz8[NF];    // 8B/(image,face): z0 fp32 (raw) + (z1-z0,z2-z0) fp16x2 (raw)

// Branch-free predicated 8B gather: single @p LDG.E.64.NC, no BSSY/BSYNC.
// VOLATILE: pins issue order and forces distinct live dest regs so all
// gathers in a batch stay in flight simultaneously (true MLP).
__device__ __forceinline__ float2 gather_pred_v(const float2* __restrict__ tab,
                                                int idx, int valid) {
    float2 r;
    const float2* addr = tab + (valid ? idx : 0);
    asm volatile(
        "{\n\t"
        ".reg .pred gp;\n\t"
        "setp.ne.s32 gp, %3, 0;\n\t"
        "mov.f32 %0, 0f00000000;\n\t"
        "mov.f32 %1, 0f00000000;\n\t"
        "@gp ld.global.nc.v2.f32 {%0,%1}, [%2];\n\t"
        "}"
        : "=f"(r.x), "=f"(r.y)
        : "l"(addr), "r"(valid));
    return r;
}

// ---------------------------------------------------------------------------
// Kernel 1: builds the RAW face-z table (independent of min/max) and computes
// min/max partials; last-finished partial block reduces them to g_mR={m,1/R}.
__global__ void __launch_bounds__(256) prep_kernel(const float* __restrict__ tv,
                                                   const int* __restrict__ faces) {
    const int tid = threadIdx.x;
    const int t = blockIdx.x * 256 + tid;
    __shared__ float smn[8], smx[8];
    __shared__ int is_last;

    // ---- raw face table: {z0, (z1-z0, z2-z0) fp16x2} -----------------------
    if (t < NF) {
        int n = t / FF;
        int f = t - n * FF;
        int v0 = __ldg(faces + 3 * f);
        int v1 = __ldg(faces + 3 * f + 1);
        int v2 = __ldg(faces + 3 * f + 2);
        long long vb = (long long)n * VV;
        float z0 = __ldg(tv + 3 * (vb + v0) + 2);
        float z1 = __ldg(tv + 3 * (vb + v1) + 2);
        float z2 = __ldg(tv + 3 * (vb + v2) + 2);
        __half2 d = __floats2half2_rn(z1 - z0, z2 - z0);
        float2 e;
        e.x = z0;
        e.y = __uint_as_float(*reinterpret_cast<unsigned int*>(&d));
        g_fz8[t] = e;
    }

    // ---- min/max partials over tv[:,:,2] (first MMBLK blocks only) ---------
    if (blockIdx.x < MMBLK) {
        float z = (t < NV) ? __ldg(tv + 3 * t + 2) : __ldg(tv + 2);
        float mn = z, mx = z;
        #pragma unroll
        for (int o = 16; o > 0; o >>= 1) {
            mn = fminf(mn, __shfl_xor_sync(0xFFFFFFFFu, mn, o));
            mx = fmaxf(mx, __shfl_xor_sync(0xFFFFFFFFu, mx, o));
        }
        int lane = tid & 31, w = tid >> 5;
        if (lane == 0) { smn[w] = mn; smx[w] = mx; }
        __syncthreads();
        if (tid == 0) {
            float bmn = smn[0], bmx = smx[0];
            #pragma unroll
            for (int k = 1; k < 8; k++) {
                bmn = fminf(bmn, smn[k]);
                bmx = fmaxf(bmx, smx[k]);
            }
            g_pmn[blockIdx.x] = bmn;
            g_pmx[blockIdx.x] = bmx;
            __threadfence();
            int c = atomicAdd(&g_done, 1);
            is_last = (c == MMBLK - 1);
        }
        __syncthreads();

        if (is_last) {
            float m = __int_as_float(0x7F800000);
            float M = -m;
            for (int k = tid; k < MMBLK; k += 256) {
                m = fminf(m, g_pmn[k]);
                M = fmaxf(M, g_pmx[k]);
            }
            #pragma unroll
            for (int o = 16; o > 0; o >>= 1) {
                m = fminf(m, __shfl_xor_sync(0xFFFFFFFFu, m, o));
                M = fmaxf(M, __shfl_xor_sync(0xFFFFFFFFu, M, o));
            }
            int lane = tid & 31, w = tid >> 5;
            if (lane == 0) { smn[w] = m; smx[w] = M; }
            __syncthreads();
            if (tid == 0) {
                float bm = smn[0], bM = smx[0];
                #pragma unroll
                for (int k = 1; k < 8; k++) {
                    bm = fminf(bm, smn[k]);
                    bM = fmaxf(bM, smx[k]);
                }
                float R = bM - bm;           // R = fl(M - m)
                g_mR = make_float2(bm, 1.0f / R);
                g_done = 0;                  // reset for next graph replay
            }
        }
    }
}

// ---------------------------------------------------------------------------
// Kernel 2: pixel interpolation. 8 px/thread with VOLATILE predicated gathers:
// all 8 LDGs pinned in issue order before any consumption -> per-warp gather
// MLP = 8 (2x R8). Streaming loads issued immediately after (independent).
__global__ void __launch_bounds__(256) pixel_kernel(
    const float* __restrict__ bary,
    const int* __restrict__ p2f,
    float* __restrict__ out)
{
    int t = blockIdx.x * blockDim.x + threadIdx.x;
    long long base = (long long)t * 8;

    int4 pa = __ldcs(reinterpret_cast<const int4*>(p2f + base));
    int4 pb = __ldcs(reinterpret_cast<const int4*>(p2f + base) + 1);
    int ps[8] = {pa.x, pa.y, pa.z, pa.w, pb.x, pb.y, pb.z, pb.w};

    // All 8 gathers issued back-to-back, all dest regs live until compute.
    float2 e0 = gather_pred_v(g_fz8, ps[0], (int)(ps[0] >= 0));
    float2 e1 = gather_pred_v(g_fz8, ps[1], (int)(ps[1] >= 0));
    float2 e2 = gather_pred_v(g_fz8, ps[2], (int)(ps[2] >= 0));
    float2 e3 = gather_pred_v(g_fz8, ps[3], (int)(ps[3] >= 0));
    float2 e4 = gather_pred_v(g_fz8, ps[4], (int)(ps[4] >= 0));
    float2 e5 = gather_pred_v(g_fz8, ps[5], (int)(ps[5] >= 0));
    float2 e6 = gather_pred_v(g_fz8, ps[6], (int)(ps[6] >= 0));
    float2 e7 = gather_pred_v(g_fz8, ps[7], (int)(ps[7] >= 0));
    float2 e[8] = {e0, e1, e2, e3, e4, e5, e6, e7};

    float2 mR = g_mR;          // uniform, L1-hit
    float m = mR.x, rcpR = mR.y;

    const float4* bp = reinterpret_cast<const float4*>(bary + base * 3);
    float4* op = reinterpret_cast<float4*>(out + base);

    #pragma unroll
    for (int h = 0; h < 2; h++) {
        float4 b0 = __ldcs(bp + 3 * h);
        float4 b1 = __ldcs(bp + 3 * h + 1);
        float4 b2 = __ldcs(bp + 3 * h + 2);
        float w[12] = {b0.x, b0.y, b0.z, b0.w, b1.x, b1.y,
                       b1.z, b1.w, b2.x, b2.y, b2.z, b2.w};
        float res[4];
        #pragma unroll
        for (int i = 0; i < 4; i++) {
            int px = 4 * h + i;
            float c1 = w[3 * i + 1], c2 = w[3 * i + 2];
            unsigned int db = __float_as_uint(e[px].y);
            __half2 dh = *reinterpret_cast<__half2*>(&db);
            float2 d = __half22float2(dh);
            float zbar = e[px].x - m + c1 * d.x + c2 * d.y;  // Σb·z - m (raw)
            float s = 1.0f - zbar * rcpR;
            res[i] = ps[px] >= 0 ? s : 0.0f;
        }
        __stcs(op + h, make_float4(res[0], res[1], res[2], res[3]));
    }
}

extern "C" void kernel_launch(void* const* d_in, const int* in_sizes, int n_in,
                              void* d_out, int out_size) {
    const float* tv = nullptr;      // 241104
    const float* bary = nullptr;    // 12582912
    const int* faces = nullptr;     // 29928
    const int* p2f = nullptr;       // 4194304
    for (int i = 0; i < n_in; i++) {
        switch (in_sizes[i]) {
            case NN * VV * 3:            tv    = (const float*)d_in[i]; break;
            case NN * HH * WW * 3:       bary  = (const float*)d_in[i]; break;
            case FF * 3:                 faces = (const int*)d_in[i];   break;
            case NN * HH * WW:           p2f   = (const int*)d_in[i];   break;
        }
    }
    float* out = (float*)d_out;

    prep_kernel<<<K1GRID, 256>>>(tv, faces);
    pixel_kernel<<<NPIX / 8 / 256, 256>>>(bary, p2f, out);
}

// round 16
// speedup vs baseline: 1.4946x; 1.2569x over previous
#include <cuda_runtime.h>
#include <cuda_fp16.h>

#define NN 16
#define VV 5023
#define FF 9976
#define HH 512
#define WW 512
#define NV (NN * VV)            // 80368
#define NF (NN * FF)            // 159616
#define NPIX (NN * HH * WW)     // 4194304
#define MMBLK 314               // blocks that produce minmax partials
#define K1GRID ((NF + 255) / 256)   // 624
#define PXGRID (NPIX / 4 / 256)     // 4096

__device__ float g_pmn[MMBLK];
__device__ float g_pmx[MMBLK];
__device__ float2 g_mR;         // {m, 1/R}
__device__ int g_done;          // zero-init; self-resets each run
__device__ float2 g_fz8[NF];    // 8B/(image,face): z0 fp32 (raw) + (z1-z0,z2-z0) fp16x2 (raw)

// Branch-free predicated 8B gather: single @p LDG.E.64.NC, no BSSY/BSYNC.
// evict_last: the table is the only reuse-bearing stream in this kernel.
// NON-volatile (R8-proven codegen: 32 regs, no spills).
__device__ __forceinline__ float2 gather_pred(const float2* __restrict__ tab,
                                              int idx, int valid) {
    float2 r;
    const float2* addr = tab + (valid ? idx : 0);
    asm("{\n\t"
        ".reg .pred gp;\n\t"
        "setp.ne.s32 gp, %3, 0;\n\t"
        "mov.f32 %0, 0f00000000;\n\t"
        "mov.f32 %1, 0f00000000;\n\t"
        "@gp ld.global.nc.L1::evict_last.v2.f32 {%0,%1}, [%2];\n\t"
        "}"
        : "=f"(r.x), "=f"(r.y)
        : "l"(addr), "r"(valid));
    return r;
}

// ---------------------------------------------------------------------------
// Kernel 1 (primary): builds the RAW face-z table (independent of min/max)
// and computes min/max partials; last-finished partial block reduces them to
// g_mR = {m, 1/R}. No early PDL trigger -> dependents see ALL writes.
__global__ void __launch_bounds__(256) prep_kernel(const float* __restrict__ tv,
                                                   const int* __restrict__ faces) {
    const int tid = threadIdx.x;
    const int t = blockIdx.x * 256 + tid;
    __shared__ float smn[8], smx[8];
    __shared__ int is_last;

    // ---- raw face table: {z0, (z1-z0, z2-z0) fp16x2} -----------------------
    if (t < NF) {
        int n = t / FF;
        int f = t - n * FF;
        int v0 = __ldg(faces + 3 * f);
        int v1 = __ldg(faces + 3 * f + 1);
        int v2 = __ldg(faces + 3 * f + 2);
        long long vb = (long long)n * VV;
        float z0 = __ldg(tv + 3 * (vb + v0) + 2);
        float z1 = __ldg(tv + 3 * (vb + v1) + 2);
        float z2 = __ldg(tv + 3 * (vb + v2) + 2);
        __half2 d = __floats2half2_rn(z1 - z0, z2 - z0);
        float2 e;
        e.x = z0;
        e.y = __uint_as_float(*reinterpret_cast<unsigned int*>(&d));
        g_fz8[t] = e;
    }

    // ---- min/max partials over tv[:,:,2] (first MMBLK blocks only) ---------
    if (blockIdx.x < MMBLK) {
        float z = (t < NV) ? __ldg(tv + 3 * t + 2) : __ldg(tv + 2);
        float mn = z, mx = z;
        #pragma unroll
        for (int o = 16; o > 0; o >>= 1) {
            mn = fminf(mn, __shfl_xor_sync(0xFFFFFFFFu, mn, o));
            mx = fmaxf(mx, __shfl_xor_sync(0xFFFFFFFFu, mx, o));
        }
        int lane = tid & 31, w = tid >> 5;
        if (lane == 0) { smn[w] = mn; smx[w] = mx; }
        __syncthreads();
        if (tid == 0) {
            float bmn = smn[0], bmx = smx[0];
            #pragma unroll
            for (int k = 1; k < 8; k++) {
                bmn = fminf(bmn, smn[k]);
                bmx = fmaxf(bmx, smx[k]);
            }
            g_pmn[blockIdx.x] = bmn;
            g_pmx[blockIdx.x] = bmx;
            __threadfence();
            int c = atomicAdd(&g_done, 1);
            is_last = (c == MMBLK - 1);
        }
        __syncthreads();

        if (is_last) {
            float m = __int_as_float(0x7F800000);
            float M = -m;
            for (int k = tid; k < MMBLK; k += 256) {
                m = fminf(m, g_pmn[k]);
                M = fmaxf(M, g_pmx[k]);
            }
            #pragma unroll
            for (int o = 16; o > 0; o >>= 1) {
                m = fminf(m, __shfl_xor_sync(0xFFFFFFFFu, m, o));
                M = fmaxf(M, __shfl_xor_sync(0xFFFFFFFFu, M, o));
            }
            int lane = tid & 31, w = tid >> 5;
            if (lane == 0) { smn[w] = m; smx[w] = M; }
            __syncthreads();
            if (tid == 0) {
                float bm = smn[0], bM = smx[0];
                #pragma unroll
                for (int k = 1; k < 8; k++) {
                    bm = fminf(bm, smn[k]);
                    bM = fmaxf(bM, smx[k]);
                }
                float R = bM - bm;           // R = fl(M - m)
                g_mR = make_float2(bm, 1.0f / R);
                g_done = 0;                  // reset for next graph replay
            }
        }
    }
}

// ---------------------------------------------------------------------------
// Kernel 2 (PDL secondary, SYNC-FIRST): blocks wait at the grid dependency
// barrier BEFORE issuing any memory op -> zero contention with prep; only the
// launch/drain gap is overlapped. Body is byte-identical to the 19.8us R8
// kernel: 4 px/thread, predicated gathers first, streaming evict-first.
__global__ void __launch_bounds__(256) pixel_kernel(
    const float* __restrict__ bary,
    const int* __restrict__ p2f,
    float* __restrict__ out)
{
    // Wait for prep_kernel completion before ANY load (HW sleep, no traffic).
    cudaGridDependencySynchronize();

    int t = blockIdx.x * blockDim.x + threadIdx.x;
    long long base = (long long)t * 4;

    int4 pv = __ldcs(reinterpret_cast<const int4*>(p2f + base));
    int ps[4] = {pv.x, pv.y, pv.z, pv.w};

    // All 4 gathers issued up front (deep LSU queue).
    float2 e[4];
    #pragma unroll
    for (int i = 0; i < 4; i++)
        e[i] = gather_pred(g_fz8, ps[i], (int)(ps[i] >= 0));

    const float4* bp = reinterpret_cast<const float4*>(bary + base * 3);
    float4 b0 = __ldcs(bp);
    float4 b1 = __ldcs(bp + 1);
    float4 b2 = __ldcs(bp + 2);
    float w[12] = {b0.x, b0.y, b0.z, b0.w, b1.x, b1.y,
                   b1.z, b1.w, b2.x, b2.y, b2.z, b2.w};

    float2 mR = g_mR;          // uniform, L1-hit
    float m = mR.x, rcpR = mR.y;

    float res[4];
    #pragma unroll
    for (int i = 0; i < 4; i++) {
        float c1 = w[3 * i + 1], c2 = w[3 * i + 2];
        unsigned int db = __float_as_uint(e[i].y);
        __half2 dh = *reinterpret_cast<__half2*>(&db);
        float2 d = __half22float2(dh);
        float zbar = e[i].x - m + c1 * d.x + c2 * d.y;   // Σb·z - m (raw)
        float s = 1.0f - zbar * rcpR;
        res[i] = ps[i] >= 0 ? s : 0.0f;
    }

    __stcs(reinterpret_cast<float4*>(out + base),
           make_float4(res[0], res[1], res[2], res[3]));
}

extern "C" void kernel_launch(void* const* d_in, const int* in_sizes, int n_in,
                              void* d_out, int out_size) {
    const float* tv = nullptr;      // 241104
    const float* bary = nullptr;    // 12582912
    const int* faces = nullptr;     // 29928
    const int* p2f = nullptr;       // 4194304
    for (int i = 0; i < n_in; i++) {
        switch (in_sizes[i]) {
            case NN * VV * 3:            tv    = (const float*)d_in[i]; break;
            case NN * HH * WW * 3:       bary  = (const float*)d_in[i]; break;
            case FF * 3:                 faces = (const int*)d_in[i];   break;
            case NN * HH * WW:           p2f   = (const int*)d_in[i];   break;
        }
    }
    float* out = (float*)d_out;

    prep_kernel<<<K1GRID, 256>>>(tv, faces);

    // PDL launch: pixel blocks may be scheduled before prep retires; the
    // sync-first cudaGridDependencySynchronize enforces the data dependency
    // without generating any competing memory traffic.
    cudaLaunchAttribute attrs[1];
    attrs[0].id = cudaLaunchAttributeProgrammaticStreamSerialization;
    attrs[0].val.programmaticStreamSerializationAllowed = 1;

    cudaLaunchConfig_t cfg = {};
    cfg.gridDim = dim3(PXGRID, 1, 1);
    cfg.blockDim = dim3(256, 1, 1);
    cfg.dynamicSmemBytes = 0;
    cfg.stream = 0;
    cfg.attrs = attrs;
    cfg.numAttrs = 1;

    cudaLaunchKernelEx(&cfg, pixel_kernel, bary, p2f, (float*)out);
}